// round 1
// baseline (speedup 1.0000x reference)
#include <cuda_runtime.h>

#define FEAT 128
#define ROWS_PER_WARP 128
#define WARPS_PER_BLOCK 8
#define UNROLL 8

// 2 = underlying batch dtype is int64 (read every other 32-bit word),
// 1 = underlying batch dtype is int32.
__device__ int g_idx_stride = 2;

// The batch array is sorted, values in [0, 10000). If the buffer really holds
// little-endian int64, every odd 32-bit word is a high word == 0. If it holds
// int32, odd words in the upper half of the (sorted) array are ~5000..9999.
__global__ void detect_dtype_kernel(const int* __restrict__ b32, int n) {
    if (blockIdx.x == 0 && threadIdx.x == 0) {
        int i1 = (n / 2) | 1;
        int i2 = (n / 2 + n / 5) | 1;
        int i3 = (n - 16) | 1;
        int s = 2;
        if (b32[i1] != 0 || b32[i2] != 0 || b32[i3] != 0) s = 1;
        g_idx_stride = s;
    }
}

__global__ void zero_kernel(float4* __restrict__ out, int n4) {
    int i = blockIdx.x * blockDim.x + threadIdx.x;
    if (i < n4) out[i] = make_float4(0.f, 0.f, 0.f, 0.f);
}

// One warp handles ROWS_PER_WARP consecutive rows. lane t owns features
// [4t, 4t+4). Runs of equal segment id accumulate in registers; atomicAdd
// fires only on run boundaries (+ final flush). Output must be pre-zeroed.
__global__ void __launch_bounds__(WARPS_PER_BLOCK * 32)
segsum_kernel(const float4* __restrict__ h, const int* __restrict__ b32,
              float* __restrict__ out, int n) {
    const int stride = g_idx_stride;
    const int lane = threadIdx.x;  // 0..31
    const long long warp = (long long)blockIdx.x * WARPS_PER_BLOCK + threadIdx.y;
    const long long row0 = warp * ROWS_PER_WARP;
    if (row0 >= n) return;
    const int rows = (int)((n - row0 < ROWS_PER_WARP) ? (n - row0) : ROWS_PER_WARP);

    const float4* __restrict__ hp = h + row0 * (FEAT / 4) + lane;
    const int* __restrict__ bp = b32 + row0 * stride;

    int seg = __ldg(bp);
    float4 acc = make_float4(0.f, 0.f, 0.f, 0.f);

    for (int r = 0; r < rows; r += UNROLL) {
        float4 v[UNROLL];
        int bb[UNROLL];
        // Batch the loads (front-loaded for MLP; addresses independent).
        #pragma unroll
        for (int j = 0; j < UNROLL; j++) {
            if (r + j < rows) {
                v[j] = hp[(long long)(r + j) * (FEAT / 4)];
                bb[j] = __ldg(bp + (long long)(r + j) * stride);
            }
        }
        #pragma unroll
        for (int j = 0; j < UNROLL; j++) {
            if (r + j < rows) {
                if (bb[j] != seg) {
                    float* o = out + (long long)seg * FEAT + lane * 4;
                    atomicAdd(o + 0, acc.x);
                    atomicAdd(o + 1, acc.y);
                    atomicAdd(o + 2, acc.z);
                    atomicAdd(o + 3, acc.w);
                    acc = make_float4(0.f, 0.f, 0.f, 0.f);
                    seg = bb[j];
                }
                acc.x += v[j].x;
                acc.y += v[j].y;
                acc.z += v[j].z;
                acc.w += v[j].w;
            }
        }
    }
    float* o = out + (long long)seg * FEAT + lane * 4;
    atomicAdd(o + 0, acc.x);
    atomicAdd(o + 1, acc.y);
    atomicAdd(o + 2, acc.z);
    atomicAdd(o + 3, acc.w);
}

extern "C" void kernel_launch(void* const* d_in, const int* in_sizes, int n_in,
                              void* d_out, int out_size) {
    const float* h = (const float*)d_in[0];      // h_t [n, 128] f32
    const int* b32 = (const int*)d_in[1];        // batch [n], int32 or int64 (detected)
    float* out = (float*)d_out;                  // [10000, 128] f32
    const int n = in_sizes[1];                   // number of nodes

    detect_dtype_kernel<<<1, 32>>>(b32, n);

    const int n4 = out_size / 4;
    zero_kernel<<<(n4 + 255) / 256, 256>>>((float4*)out, n4);

    const int nwarps = (n + ROWS_PER_WARP - 1) / ROWS_PER_WARP;
    const int nblocks = (nwarps + WARPS_PER_BLOCK - 1) / WARPS_PER_BLOCK;
    dim3 bd(32, WARPS_PER_BLOCK);
    segsum_kernel<<<nblocks, bd>>>((const float4*)h, b32, out, n);
}

// round 2
// speedup vs baseline: 1.1729x; 1.1729x over previous
#include <cuda_runtime.h>

#define FEAT 128
#define RPW 64            // rows per warp (chunk size)
#define WARPS_PER_BLOCK 8
#define UNROLL 8

__global__ void zero_kernel(float4* __restrict__ out, int n4) {
    int i = blockIdx.x * blockDim.x + threadIdx.x;
    if (i < n4) out[i] = make_float4(0.f, 0.f, 0.f, 0.f);
}

// One vectorized fp32x4 reduction instead of 4 scalar atomics (sm_90+).
__device__ __forceinline__ void flush_acc(float* __restrict__ out, int seg,
                                          int lane, float4 a) {
    float* p = out + (long long)seg * FEAT + lane * 4;
    asm volatile("red.global.add.v4.f32 [%0], {%1, %2, %3, %4};"
                 :: "l"(p), "f"(a.x), "f"(a.y), "f"(a.z), "f"(a.w)
                 : "memory");
}

// STRIDE = 2: batch is int64 (read low 32-bit word of each element)
// STRIDE = 1: batch is int32
template <int STRIDE, bool FULL>
__device__ __forceinline__ void run_chunk(const float4* __restrict__ hp,
                                          const int* __restrict__ bp,
                                          float* __restrict__ out,
                                          int rows, int lane) {
    int seg = __ldg(bp);
    float4 acc = make_float4(0.f, 0.f, 0.f, 0.f);

    #pragma unroll 1
    for (int r = 0; r < (FULL ? RPW : rows); r += UNROLL) {
        float4 v[UNROLL];
        int bb[UNROLL];
        // Front-batched independent loads for MLP. Streaming hint on h:
        // the feature data is never reused, keep L2 for indices/output.
        #pragma unroll
        for (int j = 0; j < UNROLL; j++) {
            if (FULL || r + j < rows) {
                v[j]  = __ldcs(hp + (long long)(r + j) * (FEAT / 4));
                bb[j] = __ldg(bp + (long long)(r + j) * STRIDE);
            }
        }
        #pragma unroll
        for (int j = 0; j < UNROLL; j++) {
            if (FULL || r + j < rows) {
                if (bb[j] != seg) {
                    flush_acc(out, seg, lane, acc);
                    acc = make_float4(0.f, 0.f, 0.f, 0.f);
                    seg = bb[j];
                }
                acc.x += v[j].x;
                acc.y += v[j].y;
                acc.z += v[j].z;
                acc.w += v[j].w;
            }
        }
    }
    flush_acc(out, seg, lane, acc);
}

template <int STRIDE>
__device__ __forceinline__ void run_warp(const float4* __restrict__ h,
                                         const int* __restrict__ b32,
                                         float* __restrict__ out,
                                         int n, int lane, long long row0) {
    const float4* hp = h + row0 * (FEAT / 4) + lane;
    const int* bp = b32 + row0 * STRIDE;
    if (n - row0 >= RPW) {
        run_chunk<STRIDE, true>(hp, bp, out, RPW, lane);
    } else {
        run_chunk<STRIDE, false>(hp, bp, out, (int)(n - row0), lane);
    }
}

__global__ void __launch_bounds__(WARPS_PER_BLOCK * 32)
segsum_kernel(const float4* __restrict__ h, const int* __restrict__ b32,
              float* __restrict__ out, int n) {
    const int lane = threadIdx.x;
    const long long warp = (long long)blockIdx.x * WARPS_PER_BLOCK + threadIdx.y;
    const long long row0 = warp * RPW;
    if (row0 >= n) return;

    // Dtype probe: batch is sorted with values in [0, 10000). For little-endian
    // int64 every odd 32-bit word is a zero high-word; for int32 the odd words
    // in the upper half of the sorted array are ~5000..9999. Same addresses for
    // every warp -> L2-resident broadcast, effectively free.
    const int i1 = (n / 2) | 1;
    const int i2 = (n / 2 + n / 5) | 1;
    const int i3 = (n - 16) | 1;
    const bool is64 = (__ldg(b32 + i1) == 0) && (__ldg(b32 + i2) == 0) &&
                      (__ldg(b32 + i3) == 0);

    if (is64) run_warp<2>(h, b32, out, n, lane, row0);
    else      run_warp<1>(h, b32, out, n, lane, row0);
}

extern "C" void kernel_launch(void* const* d_in, const int* in_sizes, int n_in,
                              void* d_out, int out_size) {
    const float* h = (const float*)d_in[0];   // h_t [n, 128] f32
    const int* b32 = (const int*)d_in[1];     // batch [n] (int32 or int64)
    float* out = (float*)d_out;               // [10000, 128] f32
    const int n = in_sizes[1];

    const int n4 = out_size / 4;
    zero_kernel<<<(n4 + 255) / 256, 256>>>((float4*)out, n4);

    const long long nwarps = ((long long)n + RPW - 1) / RPW;
    const int nblocks = (int)((nwarps + WARPS_PER_BLOCK - 1) / WARPS_PER_BLOCK);
    dim3 bd(32, WARPS_PER_BLOCK);
    segsum_kernel<<<nblocks, bd>>>((const float4*)h, b32, out, n);
}